// round 1
// baseline (speedup 1.0000x reference)
#include <cuda_runtime.h>
#include <math.h>

// Problem shape (fixed by reference)
#define Bc 2
#define Lc 2048
#define Hc 16
#define Ec 64
#define BHc (Bc * Hc)      // 32 (b,h) rows
#define CHc 64             // chunk length along s (must equal Ec for smem indexing)
#define NCc (Lc / CHc)     // 32 chunks per row

// Scratch (no allocations allowed in kernel_launch)
__device__ float g_E[BHc * Lc];            // e_s = exp(scale * k·w_k)
__device__ float g_cEV[BHc * NCc * Ec];    // per-chunk sum of e*V -> exclusive scan
__device__ float g_cE[BHc * NCc];          // per-chunk sum of e   -> exclusive scan

// K1: e[bh][s] = exp(0.125 * dot(keys[b,s,h,:], w_k)); one warp per s-row.
__global__ void k1_escore(const float* __restrict__ keys,
                          const float* __restrict__ w_score) {
    int warp = (blockIdx.x * blockDim.x + threadIdx.x) >> 5;
    int lane = threadIdx.x & 31;
    int bh = warp / Lc;
    int s  = warp % Lc;
    int b = bh / Hc, h = bh % Hc;
    const float2 k2 = *reinterpret_cast<const float2*>(
        keys + (((b * Lc + s) * Hc + h) * Ec) + lane * 2);
    float dot = k2.x * w_score[Ec + lane * 2] + k2.y * w_score[Ec + lane * 2 + 1];
    #pragma unroll
    for (int o = 16; o; o >>= 1) dot += __shfl_xor_sync(0xffffffffu, dot, o);
    if (lane == 0) g_E[warp] = expf(dot * 0.125f);
}

// K2: per-(bh,chunk) partial sums of e and e*V. Block = 64 threads = d channels.
__global__ void k2_chunksum(const float* __restrict__ values) {
    int bh = blockIdx.x / NCc, c = blockIdx.x % NCc;
    int b = bh / Hc, h = bh % Hc;
    int d = threadIdx.x;
    __shared__ float se[CHc];
    se[d] = g_E[bh * Lc + c * CHc + d];
    __syncthreads();
    const float* vbase = values + ((b * Lc + c * CHc) * Hc + h) * Ec + d;
    float acc = 0.f, sum = 0.f;
    #pragma unroll 8
    for (int i = 0; i < CHc; i++) {
        float e = se[i];
        sum += e;
        acc += e * vbase[i * Hc * Ec];
    }
    g_cEV[(bh * NCc + c) * Ec + d] = acc;
    if (d == 0) g_cE[bh * NCc + c] = sum;
}

// K3: exclusive scan of chunk sums along c, per bh. 32 blocks x 64 threads; tiny.
__global__ void k3_scan() {
    int bh = blockIdx.x;
    int d = threadIdx.x;
    float run = 0.f, runE = 0.f;
    for (int c = 0; c < NCc; c++) {
        int idx = (bh * NCc + c) * Ec + d;
        float t = g_cEV[idx];
        g_cEV[idx] = run;
        run += t;
        if (d == 0) {
            float te = g_cE[bh * NCc + c];
            g_cE[bh * NCc + c] = runE;
            runE += te;
        }
    }
}

// K4: per-(bh,chunk): start from exclusive offsets, run inclusive scan within
// chunk, write out[b,l,h,d] = accEV / accE.
__global__ void k4_output(const float* __restrict__ values,
                          float* __restrict__ out) {
    int bh = blockIdx.x / NCc, c = blockIdx.x % NCc;
    int b = bh / Hc, h = bh % Hc;
    int d = threadIdx.x;
    __shared__ float se[CHc];
    se[d] = g_E[bh * Lc + c * CHc + d];
    __syncthreads();
    float accEV = g_cEV[(bh * NCc + c) * Ec + d];
    float accE  = g_cE[bh * NCc + c];
    const int rowstride = Hc * Ec;
    const float* vbase = values + ((b * Lc + c * CHc) * Hc + h) * Ec + d;
    float*       obase = out    + ((b * Lc + c * CHc) * Hc + h) * Ec + d;
    #pragma unroll 4
    for (int i = 0; i < CHc; i++) {
        float e = se[i];
        accE  += e;
        accEV += e * vbase[i * rowstride];
        obase[i * rowstride] = __fdividef(accEV, accE);
    }
}

extern "C" void kernel_launch(void* const* d_in, const int* in_sizes, int n_in,
                              void* d_out, int out_size) {
    // inputs: 0=queries (UNUSED: a_q cancels in softmax), 1=keys, 2=values,
    //         3=w_score, 4=b_score (UNUSED: cancels)
    const float* keys   = (const float*)d_in[1];
    const float* values = (const float*)d_in[2];
    const float* w      = (const float*)d_in[3];
    float* out = (float*)d_out;

    k1_escore<<<(BHc * Lc) / 8, 256>>>(keys, w);   // 8 warps/block
    k2_chunksum<<<BHc * NCc, CHc>>>(values);
    k3_scan<<<BHc, Ec>>>();
    k4_output<<<BHc * NCc, Ec>>>(values, out);
}

// round 2
// speedup vs baseline: 2.2846x; 2.2846x over previous
#include <cuda_runtime.h>
#include <math.h>

// Shape fixed by reference: B=2, L=2048, H=16, E=64
#define B_  2
#define L_  2048
#define H_  16
#define E_  64
#define BH_ 32            // B*H chains
#define CH_ 64            // chunk length along s
#define NC_ 32            // chunks per chain
#define HE_ 1024          // H*E row stride in floats
#define NBLK (BH_ * NC_)  // 1024 blocks

// Scratch (__device__ globals; no allocations allowed)
__device__ float g_agg [NBLK * E_];  // per-chunk sum of e*V
__device__ float g_aggE[NBLK];       // per-chunk sum of e
__device__ int   g_flag[NBLK];       // publish flags

__global__ void reset_flags() { g_flag[threadIdx.x] = 0; }

// One block per (bh, chunk). Single pass over keys+values.
__global__ __launch_bounds__(256, 8) void fused_scan_attn(
    const float* __restrict__ keys,
    const float* __restrict__ values,
    const float* __restrict__ w_score,
    float* __restrict__ out)
{
    __shared__ float sV[CH_ * E_];   // 16 KB V tile
    __shared__ float se[CH_];        // e-scores for this chunk

    const int tid = threadIdx.x;
    const int blk = blockIdx.x;
    const int bh  = blk >> 5;        // / NC_
    const int c   = blk & 31;        // % NC_
    const int b   = bh >> 4;         // / H_
    const int h   = bh & 15;         // % H_
    // element offset of row (b, s0=c*CH_, h, 0); max ~4.2M < 2^31
    const int base = ((b * L_ + c * CH_) * H_ + h) * E_;

    // ---- phase 1: e[r] = exp(scale * dot(K[row r], w_k)); warp handles 8 rows
    {
        const int w = tid >> 5, lane = tid & 31;
        const float2 wk = reinterpret_cast<const float2*>(w_score + E_)[lane];
        #pragma unroll
        for (int i = 0; i < 8; i++) {
            const int r = w * 8 + i;
            const float2 kk =
                reinterpret_cast<const float2*>(keys + base + r * HE_)[lane];
            float d = kk.x * wk.x + kk.y * wk.y;
            #pragma unroll
            for (int o = 16; o; o >>= 1) d += __shfl_xor_sync(0xffffffffu, d, o);
            if (lane == 0) se[r] = __expf(d * 0.125f);
        }
    }

    // ---- phase 2: stage V tile into smem (float4, coalesced)
    {
        const float4* vg = reinterpret_cast<const float4*>(values + base);
        float4* sv4 = reinterpret_cast<float4*>(sV);
        #pragma unroll
        for (int i = 0; i < 4; i++) {
            const int idx = tid + i * 256;       // float4 index 0..1023
            const int r = idx >> 4, d4 = idx & 15;
            sv4[idx] = vg[r * (HE_ / 4) + d4];
        }
    }
    __syncthreads();

    // ---- phase 3: local chunk aggregates (d-parallel over 64 channels)
    if (tid < E_) {
        float sumE = 0.f, sumEV = 0.f;
        #pragma unroll 8
        for (int r = 0; r < CH_; r++) {
            const float e = se[r];
            sumE += e;
            sumEV = fmaf(e, sV[r * E_ + tid], sumEV);
        }
        g_agg[blk * E_ + tid] = sumEV;
        if (tid == 0) g_aggE[blk] = sumE;
        __threadfence();                 // order agg stores before flag
    }
    __syncthreads();
    if (tid == 0) atomicExch(&g_flag[blk], 1);

    // ---- lookback: wait for ALL predecessors in this chain (≤31), no chain
    if (tid < c) {
        while (atomicAdd(&g_flag[bh * NC_ + tid], 0) == 0) { }
        __threadfence();                 // acquire predecessors' agg stores
    }
    __syncthreads();

    // ---- phase 4: exclusive prefix + in-chunk inclusive scan + output
    if (tid < E_) {
        float preEV = 0.f, preE = 0.f;
        for (int t = 0; t < c; t++) {
            preEV += g_agg[(bh * NC_ + t) * E_ + tid];
            preE  += g_aggE[bh * NC_ + t];
        }
        float accE = preE, accEV = preEV;
        float* o = out + base + tid;
        #pragma unroll 4
        for (int r = 0; r < CH_; r++) {
            const float e = se[r];
            accE += e;
            accEV = fmaf(e, sV[r * E_ + tid], accEV);
            o[r * HE_] = __fdividef(accEV, accE);
        }
    }
}

extern "C" void kernel_launch(void* const* d_in, const int* in_sizes, int n_in,
                              void* d_out, int out_size) {
    // inputs: 0=queries (unused: a_q term cancels in softmax), 1=keys,
    //         2=values, 3=w_score, 4=b_score (unused: cancels)
    const float* keys   = (const float*)d_in[1];
    const float* values = (const float*)d_in[2];
    const float* w      = (const float*)d_in[3];
    float* out = (float*)d_out;

    reset_flags<<<1, NBLK>>>();
    fused_scan_attn<<<NBLK, 256>>>(keys, values, w, out);
}